// round 10
// baseline (speedup 1.0000x reference)
#include <cuda_runtime.h>
#include <cuda_bf16.h>
#include <math.h>
#include <stdint.h>

// Problem constants
#define B_  4
#define N_  512
#define D_  768
#define F_  3072
#define H_  12
#define HD_ 64
#define M_  (B_*N_)   // 2048 tokens
#define NBLOCKS 12
#define QKVN (3*D_)   // 2304

// =================== scratch (static device globals) ========================
__device__ __align__(256) __nv_bfloat16 g_lns [2L*M_*D_];
__device__ __align__(256) __nv_bfloat16 g_qkvs[2L*M_*QKVN];
__device__ __align__(256) __nv_bfloat16 g_ffs [2L*M_*F_];
__device__ __align__(256) float         g_ffw [3L*M_*F_];   // split-K fp32 partials
__device__ __align__(256) __nv_bfloat16 g_wqkv[2L*QKVN*D_];
__device__ __align__(256) __nv_bfloat16 g_w0t [2L*D_*F_];
__device__ __align__(256) __nv_bfloat16 g_w1t [2L*D_*F_];
__device__ float g_bqkv[QKVN];

// =================== PTX helpers ===========================================
__device__ __forceinline__ uint32_t smem_u32(const void* p){
    uint32_t a;
    asm("{ .reg .u64 t; cvta.to.shared.u64 t, %1; cvt.u32.u64 %0, t; }" : "=r"(a) : "l"(p));
    return a;
}
__device__ __forceinline__ void cpa16(uint32_t d, const void* s){
    asm volatile("cp.async.cg.shared.global [%0], [%1], 16;" :: "r"(d), "l"(s));
}
#define CP_COMMIT() asm volatile("cp.async.commit_group;" ::: "memory")

__device__ __forceinline__ void ldsm4(uint32_t* r, uint32_t addr){
    asm volatile("ldmatrix.sync.aligned.m8n8.x4.shared.b16 {%0,%1,%2,%3}, [%4];"
                 : "=r"(r[0]), "=r"(r[1]), "=r"(r[2]), "=r"(r[3]) : "r"(addr));
}
__device__ __forceinline__ void ldsm4t(uint32_t* r, uint32_t addr){
    asm volatile("ldmatrix.sync.aligned.m8n8.x4.trans.shared.b16 {%0,%1,%2,%3}, [%4];"
                 : "=r"(r[0]), "=r"(r[1]), "=r"(r[2]), "=r"(r[3]) : "r"(addr));
}
__device__ __forceinline__ void mma16816(float* c, const uint32_t* a, const uint32_t* b){
    asm volatile(
        "mma.sync.aligned.m16n8k16.row.col.f32.bf16.bf16.f32 "
        "{%0,%1,%2,%3}, {%4,%5,%6,%7}, {%8,%9}, {%0,%1,%2,%3};"
        : "+f"(c[0]), "+f"(c[1]), "+f"(c[2]), "+f"(c[3])
        : "r"(a[0]), "r"(a[1]), "r"(a[2]), "r"(a[3]), "r"(b[0]), "r"(b[1]));
}
__device__ __forceinline__ void redg2(float* p, float a, float b){
    asm volatile("red.global.v2.f32.add [%0], {%1, %2};" :: "l"(p), "f"(a), "f"(b) : "memory");
}
__device__ __forceinline__ float gelu_exact(float v){
    return 0.5f * v * (1.0f + erff(v * 0.70710678118654752f));
}
__device__ __forceinline__ uint32_t swz(uint32_t off){ return off ^ ((off >> 3) & 0x70); }
__device__ __forceinline__ uint32_t pkh(float x, float y){
    __nv_bfloat162 h; h.x = __float2bfloat16(x); h.y = __float2bfloat16(y);
    return *(uint32_t*)&h;
}
__device__ __forceinline__ uint32_t pkl(float x, float y){
    float rx = x - __bfloat162float(__float2bfloat16(x));
    float ry = y - __bfloat162float(__float2bfloat16(y));
    __nv_bfloat162 h; h.x = __float2bfloat16(rx); h.y = __float2bfloat16(ry);
    return *(uint32_t*)&h;
}

// =================== LayerNorm: warp per row, 4 rows/CTA ====================
__global__ void __launch_bounds__(128)
ln_kernel(const float* __restrict__ x,
          const float* __restrict__ g,
          const float* __restrict__ be,
          __nv_bfloat16* __restrict__ out, long plane)
{
    const int w = threadIdx.x >> 5, l = threadIdx.x & 31;
    const long row = (long)blockIdx.x * 4 + w;
    const float* xr = x + row * D_;

    float4 v[6];
    float s = 0.f;
    #pragma unroll
    for (int i = 0; i < 6; i++) {
        v[i] = *(const float4*)(xr + i * 128 + l * 4);
        s += v[i].x + v[i].y + v[i].z + v[i].w;
    }
    #pragma unroll
    for (int o = 16; o > 0; o >>= 1) s += __shfl_xor_sync(0xFFFFFFFFu, s, o);
    const float mu = s * (1.0f / D_);

    float vs = 0.f;
    #pragma unroll
    for (int i = 0; i < 6; i++) {
        float a = v[i].x - mu, b2 = v[i].y - mu, c = v[i].z - mu, d = v[i].w - mu;
        vs += a*a + b2*b2 + c*c + d*d;
    }
    #pragma unroll
    for (int o = 16; o > 0; o >>= 1) vs += __shfl_xor_sync(0xFFFFFFFFu, vs, o);
    const float inv = rsqrtf(vs * (1.0f / D_) + 1e-5f);

    __nv_bfloat16* orow = out + row * D_;
    #pragma unroll
    for (int i = 0; i < 6; i++) {
        const int col = i * 128 + l * 4;
        float4 gg = *(const float4*)(g  + col);
        float4 bb = *(const float4*)(be + col);
        float y0 = (v[i].x - mu) * inv * gg.x + bb.x;
        float y1 = (v[i].y - mu) * inv * gg.y + bb.y;
        float y2 = (v[i].z - mu) * inv * gg.z + bb.z;
        float y3 = (v[i].w - mu) * inv * gg.w + bb.w;
        uint2 hp; hp.x = pkh(y0, y1); hp.y = pkh(y2, y3);
        *(uint2*)(orow + col) = hp;
        uint2 lp; lp.x = pkl(y0, y1); lp.y = pkl(y2, y3);
        *(uint2*)(orow + plane + col) = lp;
    }
}

// =================== Weight transpose + split (batched) =====================
__device__ __forceinline__ void tsplit_tile(const float* __restrict__ in,
                                            __nv_bfloat16* __restrict__ out,
                                            int ldin, int ldout, long plane,
                                            int c0, int r0, int tx, int ty,
                                            float (*t)[33])
{
    #pragma unroll
    for (int i = 0; i < 32; i += 8)
        t[ty+i][tx] = in[(long)(r0+ty+i) * ldin + c0 + tx];
    __syncthreads();
    #pragma unroll
    for (int i = 0; i < 32; i += 8) {
        float v = t[tx][ty+i];
        __nv_bfloat16 h = __float2bfloat16(v);
        long o = (long)(c0+ty+i) * ldout + r0 + tx;
        out[o] = h;
        out[o + plane] = __float2bfloat16(v - __bfloat162float(h));
    }
}

// launch 1: Wq/Wk/Wv (z = 0/1/2), each [D_, D_] -> wqkv + z*D_*D_
__global__ void tsplit_qkv(const float* __restrict__ Wq, const float* __restrict__ Wk,
                           const float* __restrict__ Wv, __nv_bfloat16* __restrict__ out)
{
    __shared__ float t[32][33];
    const int z = blockIdx.z;
    const float* in = (z == 0) ? Wq : (z == 1) ? Wk : Wv;
    tsplit_tile(in, out + (long)z * D_ * D_, D_, D_, (long)QKVN * D_,
                blockIdx.x * 32, blockIdx.y * 32, threadIdx.x, threadIdx.y, t);
}

// launch 2: W0 (z=0), W1 (z=1), bias concat (z=2)
__global__ void tsplit_mlp(const float* __restrict__ W0, const float* __restrict__ W1,
                           __nv_bfloat16* __restrict__ w0t, __nv_bfloat16* __restrict__ w1t,
                           const float* __restrict__ bq, const float* __restrict__ bk,
                           const float* __restrict__ bv, float* __restrict__ bqkv)
{
    __shared__ float t[32][33];
    const int z = blockIdx.z;
    if (z == 2) {
        if (blockIdx.y == 0) {
            int i = blockIdx.x * 256 + threadIdx.y * 32 + threadIdx.x;
            if (i < QKVN)
                bqkv[i] = (i < D_) ? bq[i] : (i < 2*D_) ? bk[i - D_] : bv[i - 2*D_];
        }
        return;
    }
    const int bx = z ? blockIdx.y : blockIdx.x;
    const int by = z ? blockIdx.x : blockIdx.y;
    if (z == 0)
        tsplit_tile(W0, w0t, F_, D_, (long)D_ * F_, bx * 32, by * 32,
                    threadIdx.x, threadIdx.y, t);
    else
        tsplit_tile(W1, w1t, D_, F_, (long)D_ * F_, bx * 32, by * 32,
                    threadIdx.x, threadIdx.y, t);
}

// =================== GELU + split combine (MLP1 split-K x3) =================
__global__ void __launch_bounds__(256)
gelu_split(const float* __restrict__ a, const float* __restrict__ b,
           const float* __restrict__ c,
           const float* __restrict__ bias, __nv_bfloat16* __restrict__ out, long plane)
{
    const long i0 = ((long)blockIdx.x * 256 + threadIdx.x) * 4;
    const int col = (int)(i0 % F_);
    float4 va = *(const float4*)(a + i0);
    float4 vb = *(const float4*)(b + i0);
    float4 vc = *(const float4*)(c + i0);
    float4 bs = *(const float4*)(bias + col);
    float y0 = gelu_exact(va.x + vb.x + vc.x + bs.x);
    float y1 = gelu_exact(va.y + vb.y + vc.y + bs.y);
    float y2 = gelu_exact(va.z + vb.z + vc.z + bs.z);
    float y3 = gelu_exact(va.w + vb.w + vc.w + bs.w);
    uint2 hp; hp.x = pkh(y0, y1); hp.y = pkh(y2, y3);
    *(uint2*)(out + i0) = hp;
    uint2 lp; lp.x = pkl(y0, y1); lp.y = pkl(y2, y3);
    *(uint2*)(out + plane + i0) = lp;
}

// =================== HMMA GEMM: 512 thr, 16 warps 4x4, 32x32 warp tile =====
// 3-stage cp.async pipeline, 2 CTAs/SM (32 warps/SM).
// EPI 0: fp32 C[z-buffer] = v | EPI 3: split-bf16 C = v + bias
// EPI 5: fp32 red.add(C, v [+ bias if z==0])
template<int EPI>
__global__ void __launch_bounds__(512, 2)
gemm_mma(const __nv_bfloat16* __restrict__ A, const __nv_bfloat16* __restrict__ B,
         const float* __restrict__ bias, void* __restrict__ Cv,
         int K, int lda, int ldb, int ldc,
         long planeA, long planeB, long planeC)
{
    extern __shared__ char sm[];
    constexpr int ABYTES = 128 * 128;
    constexpr int BBYTES = 128 * 128;
    constexpr int STG = ABYTES + BBYTES;

    const uint32_t smb = (smem_u32(sm) + 127) & ~127u;

    const int tid = threadIdx.x;
    const int wid = tid >> 5, l = tid & 31;
    const int wm = (wid & 3) * 32;
    const int wn = (wid >> 2) * 32;

    const long bm = (long)blockIdx.y * 128;
    const long bn = (long)blockIdx.x * 128;
    const long koff = (long)blockIdx.z * K;

    float* Cf = (float*)Cv;
    if (EPI == 0) Cf += (long)blockIdx.z * planeC;
    __nv_bfloat16* Cb = (__nv_bfloat16*)Cv;

    const int kch = K / 64;
    const int NC = 3 * kch;

    float acc[2][4][4];
    #pragma unroll
    for (int i = 0; i < 2; i++)
        #pragma unroll
        for (int j = 0; j < 4; j++)
            #pragma unroll
            for (int q = 0; q < 4; q++) acc[i][j][q] = 0.f;

    auto load_chunk = [&](int c, int st) {
        const int p  = c / kch;
        const long kk = koff + (long)(c - p * kch) * 64;
        const __nv_bfloat16* Ap = A + ((p == 2) ? planeA : 0) + kk;
        const __nv_bfloat16* Bp = B + ((p == 1) ? planeB : 0) + kk;
        const uint32_t sA = smb + st * STG;
        const uint32_t sB = sA + ABYTES;
        #pragma unroll
        for (int j = 0; j < 2; j++) {
            int idx = tid * 2 + j;                 // 0..1023
            int row = idx >> 3, c16 = (idx & 7) * 16;
            cpa16(sA + swz(row * 128 + c16),
                  (const char*)(Ap + (bm + row) * lda) + c16);
        }
        #pragma unroll
        for (int j = 0; j < 2; j++) {
            int idx = tid * 2 + j;
            int row = idx >> 3, c16 = (idx & 7) * 16;
            cpa16(sB + swz(row * 128 + c16),
                  (const char*)(Bp + (bn + row) * ldb) + c16);
        }
        CP_COMMIT();
    };

    auto compute = [&](int st) {
        const uint32_t bA = smb + st * STG;
        const uint32_t bB = bA + ABYTES;
        #pragma unroll
        for (int kk2 = 0; kk2 < 4; kk2++) {
            uint32_t a[2][4];
            #pragma unroll
            for (int tm = 0; tm < 2; tm++) {
                int row = wm + tm * 16 + (l & 15);
                uint32_t off = row * 128 + kk2 * 32 + ((l >> 4) * 16);
                ldsm4(a[tm], bA + swz(off));
            }
            #pragma unroll
            for (int nb = 0; nb < 2; nb++) {
                uint32_t b[4];
                int rowB = wn + nb * 16 + (l & 7) + ((l >> 4) << 3);
                uint32_t off = rowB * 128 + kk2 * 32 + (((l >> 3) & 1) * 16);
                ldsm4(b, bB + swz(off));
                #pragma unroll
                for (int tm = 0; tm < 2; tm++) {
                    mma16816(acc[tm][2*nb],   a[tm], b);
                    mma16816(acc[tm][2*nb+1], a[tm], b + 2);
                }
            }
        }
    };

    load_chunk(0, 0);
    load_chunk(1, 1);
    for (int c = 0; c < NC; c++) {
        if (c < NC - 1) asm volatile("cp.async.wait_group 1;" ::: "memory");
        else            asm volatile("cp.async.wait_group 0;" ::: "memory");
        __syncthreads();
        if (c + 2 < NC) load_chunk(c + 2, (c + 2) % 3);
        compute(c % 3);
    }

    // -------- epilogue --------
    const bool addb = (EPI != 5) || (blockIdx.z == 0);
    #pragma unroll
    for (int tm = 0; tm < 2; tm++) {
        #pragma unroll
        for (int nf = 0; nf < 4; nf++) {
            const long col = bn + wn + nf * 8 + (l & 3) * 2;
            const float bb0 = (bias && addb) ? bias[col]     : 0.f;
            const float bb1 = (bias && addb) ? bias[col + 1] : 0.f;
            #pragma unroll
            for (int h = 0; h < 2; h++) {
                const long row = bm + wm + tm * 16 + (l >> 2) + h * 8;
                float v0 = acc[tm][nf][2*h]     + bb0;
                float v1 = acc[tm][nf][2*h + 1] + bb1;
                const long idx = row * (long)ldc + col;
                if (EPI == 0) {
                    float2 t; t.x = v0; t.y = v1;
                    *(float2*)(Cf + idx) = t;
                } else if (EPI == 5) {
                    redg2(Cf + idx, v0, v1);
                } else {
                    __nv_bfloat16 h0 = __float2bfloat16(v0);
                    __nv_bfloat16 h1 = __float2bfloat16(v1);
                    __nv_bfloat162 hv; hv.x = h0; hv.y = h1;
                    *(__nv_bfloat162*)(Cb + idx) = hv;
                    __nv_bfloat162 lv;
                    lv.x = __float2bfloat16(v0 - __bfloat162float(h0));
                    lv.y = __float2bfloat16(v1 - __bfloat162float(h1));
                    *(__nv_bfloat162*)(Cb + idx + planeC) = lv;
                }
            }
        }
    }
}

// =================== Fused flash attention =================================
__global__ void __launch_bounds__(256, 2)
flash_attn(const __nv_bfloat16* __restrict__ qkv, float* __restrict__ x, long planeQ)
{
    extern __shared__ char sm[];
    const uint32_t smb = (smem_u32(sm) + 127) & ~127u;
    const uint32_t Qb = smb;             // Q: hi 16K + lo 16K
    const uint32_t St = smb + 32768;     // 2 stages x 32K

    const int tid = threadIdx.x, wid = tid >> 5, l = tid & 31;
    const int qt = blockIdx.x, z = blockIdx.y;
    const int b = z / H_, h = z % H_;
    const long tokq = (long)b * N_ + qt * 128;

    #pragma unroll
    for (int p = 0; p < 2; p++)
        #pragma unroll
        for (int j = 0; j < 4; j++) {
            int idx = tid * 4 + j;
            int row = idx >> 3, c16 = idx & 7;
            cpa16(Qb + p*16384 + swz(row*128 + c16*16),
                  qkv + p*planeQ + (tokq + row)*QKVN + h*HD_ + c16*8);
        }

    auto load_kv = [&](int c, int st) {
        const uint32_t base = St + st * 32768;
        #pragma unroll
        for (int p = 0; p < 2; p++)
            #pragma unroll
            for (int j = 0; j < 2; j++) {
                int idx = tid * 2 + j;
                int row = idx >> 3, c16 = idx & 7;
                const long tok = (long)b * N_ + c * 64 + row;
                cpa16(base + p*8192 + swz(row*128 + c16*16),
                      qkv + p*planeQ + tok*QKVN + D_ + h*HD_ + c16*8);
                cpa16(base + 16384 + p*8192 + swz(row*128 + c16*16),
                      qkv + p*planeQ + tok*QKVN + 2*D_ + h*HD_ + c16*8);
            }
        CP_COMMIT();
    };

    load_kv(0, 0);
    load_kv(1, 1);

    float o[8][4];
    #pragma unroll
    for (int i = 0; i < 8; i++)
        #pragma unroll
        for (int q = 0; q < 4; q++) o[i][q] = 0.f;
    float m0 = -1e30f, m1 = -1e30f, rs0 = 0.f, rs1 = 0.f;

    const int NCH = N_ / 64;   // 8
    for (int c = 0; c < NCH; c++) {
        if (c < NCH - 1) asm volatile("cp.async.wait_group 1;" ::: "memory");
        else             asm volatile("cp.async.wait_group 0;" ::: "memory");
        __syncthreads();

        const uint32_t Kst = St + (c & 1) * 32768;
        const uint32_t Vst = Kst + 16384;

        float s[8][4];
        #pragma unroll
        for (int i = 0; i < 8; i++)
            #pragma unroll
            for (int q = 0; q < 4; q++) s[i][q] = 0.f;

        #pragma unroll
        for (int kk = 0; kk < 4; kk++) {
            uint32_t ah[4], al[4];
            {
                int row = wid * 16 + (l & 15);
                uint32_t off = row * 128 + kk * 32 + ((l >> 4) * 16);
                ldsm4(ah, Qb + swz(off));
                ldsm4(al, Qb + 16384 + swz(off));
            }
            #pragma unroll
            for (int nb = 0; nb < 4; nb++) {
                int rowB = nb * 16 + (l & 7) + ((l >> 4) << 3);
                uint32_t off = rowB * 128 + kk * 32 + (((l >> 3) & 1) * 16);
                uint32_t bh[4], bl[4];
                ldsm4(bh, Kst + swz(off));
                ldsm4(bl, Kst + 8192 + swz(off));
                mma16816(s[2*nb],   ah, bh); mma16816(s[2*nb+1], ah, bh + 2);
                mma16816(s[2*nb],   ah, bl); mma16816(s[2*nb+1], ah, bl + 2);
                mma16816(s[2*nb],   al, bh); mma16816(s[2*nb+1], al, bh + 2);
            }
        }
        #pragma unroll
        for (int i = 0; i < 8; i++)
            #pragma unroll
            for (int q = 0; q < 4; q++) s[i][q] *= 0.125f;

        float mx0 = -1e30f, mx1 = -1e30f;
        #pragma unroll
        for (int i = 0; i < 8; i++) {
            mx0 = fmaxf(mx0, fmaxf(s[i][0], s[i][1]));
            mx1 = fmaxf(mx1, fmaxf(s[i][2], s[i][3]));
        }
        mx0 = fmaxf(mx0, __shfl_xor_sync(0xFFFFFFFFu, mx0, 1));
        mx0 = fmaxf(mx0, __shfl_xor_sync(0xFFFFFFFFu, mx0, 2));
        mx1 = fmaxf(mx1, __shfl_xor_sync(0xFFFFFFFFu, mx1, 1));
        mx1 = fmaxf(mx1, __shfl_xor_sync(0xFFFFFFFFu, mx1, 2));
        float nm0 = fmaxf(m0, mx0), nm1 = fmaxf(m1, mx1);
        float sc0 = __expf(m0 - nm0), sc1 = __expf(m1 - nm1);
        m0 = nm0; m1 = nm1;

        float sum0 = 0.f, sum1 = 0.f;
        #pragma unroll
        for (int i = 0; i < 8; i++) {
            s[i][0] = __expf(s[i][0] - m0);
            s[i][1] = __expf(s[i][1] - m0);
            s[i][2] = __expf(s[i][2] - m1);
            s[i][3] = __expf(s[i][3] - m1);
            sum0 += s[i][0] + s[i][1];
            sum1 += s[i][2] + s[i][3];
        }
        sum0 += __shfl_xor_sync(0xFFFFFFFFu, sum0, 1);
        sum0 += __shfl_xor_sync(0xFFFFFFFFu, sum0, 2);
        sum1 += __shfl_xor_sync(0xFFFFFFFFu, sum1, 1);
        sum1 += __shfl_xor_sync(0xFFFFFFFFu, sum1, 2);
        rs0 = rs0 * sc0 + sum0;
        rs1 = rs1 * sc1 + sum1;

        #pragma unroll
        for (int i = 0; i < 8; i++) {
            o[i][0] *= sc0; o[i][1] *= sc0;
            o[i][2] *= sc1; o[i][3] *= sc1;
        }

        #pragma unroll
        for (int kc = 0; kc < 4; kc++) {
            uint32_t ah[4], al[4];
            ah[0] = pkh(s[2*kc][0],   s[2*kc][1]);
            ah[1] = pkh(s[2*kc][2],   s[2*kc][3]);
            ah[2] = pkh(s[2*kc+1][0], s[2*kc+1][1]);
            ah[3] = pkh(s[2*kc+1][2], s[2*kc+1][3]);
            al[0] = pkl(s[2*kc][0],   s[2*kc][1]);
            al[1] = pkl(s[2*kc][2],   s[2*kc][3]);
            al[2] = pkl(s[2*kc+1][0], s[2*kc+1][1]);
            al[3] = pkl(s[2*kc+1][2], s[2*kc+1][3]);
            #pragma unroll
            for (int nb = 0; nb < 4; nb++) {
                uint32_t off = (kc*16 + (l & 15)) * 128 + nb*32 + ((l >> 4) * 16);
                uint32_t bh[4], bl[4];
                ldsm4t(bh, Vst + swz(off));
                ldsm4t(bl, Vst + 8192 + swz(off));
                mma16816(o[2*nb],   ah, bh); mma16816(o[2*nb+1], ah, bh + 2);
                mma16816(o[2*nb],   ah, bl); mma16816(o[2*nb+1], ah, bl + 2);
                mma16816(o[2*nb],   al, bh); mma16816(o[2*nb+1], al, bh + 2);
            }
        }

        __syncthreads();
        if (c + 2 < NCH) load_kv(c + 2, c & 1);
    }

    const float inv0 = 1.f / rs0, inv1 = 1.f / rs1;
    const long tok0 = tokq + wid * 16 + (l >> 2);
    const long col = h * HD_ + (l & 3) * 2;
    #pragma unroll
    for (int nf = 0; nf < 8; nf++) {
        float2* p0 = (float2*)(x + tok0 * D_ + col + nf * 8);
        float2 t0 = *p0;
        t0.x += o[nf][0] * inv0; t0.y += o[nf][1] * inv0;
        *p0 = t0;
        float2* p1 = (float2*)(x + (tok0 + 8) * D_ + col + nf * 8);
        float2 t1 = *p1;
        t1.x += o[nf][2] * inv1; t1.y += o[nf][3] * inv1;
        *p1 = t1;
    }
}

// =================== driver ================================================
extern "C" void kernel_launch(void* const* d_in, const int* in_sizes, int n_in,
                              void* d_out, int out_size)
{
    const float* x0  = (const float*)d_in[0];
    const float* Wq  = (const float*)d_in[1];
    const float* bq  = (const float*)d_in[2];
    const float* Wk  = (const float*)d_in[3];
    const float* bk  = (const float*)d_in[4];
    const float* Wv  = (const float*)d_in[5];
    const float* bv  = (const float*)d_in[6];
    const float* g1  = (const float*)d_in[7];
    const float* be1 = (const float*)d_in[8];
    const float* g2  = (const float*)d_in[9];
    const float* be2 = (const float*)d_in[10];
    const float* W0  = (const float*)d_in[11];
    const float* b0  = (const float*)d_in[12];
    const float* W1  = (const float*)d_in[13];
    const float* b1  = (const float*)d_in[14];

    float* x = (float*)d_out;

    __nv_bfloat16 *lns, *qkvs, *ffs, *wqkv, *w0t, *w1t;
    float *bqkv, *ffw;
    cudaGetSymbolAddress((void**)&lns,  g_lns);
    cudaGetSymbolAddress((void**)&qkvs, g_qkvs);
    cudaGetSymbolAddress((void**)&ffs,  g_ffs);
    cudaGetSymbolAddress((void**)&ffw,  g_ffw);
    cudaGetSymbolAddress((void**)&wqkv, g_wqkv);
    cudaGetSymbolAddress((void**)&w0t,  g_w0t);
    cudaGetSymbolAddress((void**)&w1t,  g_w1t);
    cudaGetSymbolAddress((void**)&bqkv, g_bqkv);

    const int SMG = 3 * (128*128 + 128*128) + 256;   // 98560
    const int SMF = 32768 + 2 * 32768 + 256;          // 98560
    cudaFuncSetAttribute(gemm_mma<0>, cudaFuncAttributeMaxDynamicSharedMemorySize, SMG);
    cudaFuncSetAttribute(gemm_mma<3>, cudaFuncAttributeMaxDynamicSharedMemorySize, SMG);
    cudaFuncSetAttribute(gemm_mma<5>, cudaFuncAttributeMaxDynamicSharedMemorySize, SMG);
    cudaFuncSetAttribute(flash_attn,  cudaFuncAttributeMaxDynamicSharedMemorySize, SMF);

    cudaMemcpyAsync(x, x0, sizeof(float)*M_*D_, cudaMemcpyDeviceToDevice);

    // ---- weight preprocessing: 2 launches so captured #4 = QKV GEMM ----
    dim3 tb(32, 8);
    tsplit_qkv<<<dim3(D_/32, D_/32, 3), tb>>>(Wq, Wk, Wv, wqkv);                 // 1
    tsplit_mlp<<<dim3(F_/32, D_/32, 3), tb>>>(W0, W1, w0t, w1t, bq, bk, bv, bqkv); // 2

    const long MD   = (long)M_ * D_;
    const long MQ   = (long)M_ * QKVN;
    const long MF   = (long)M_ * F_;
    const long WDF  = (long)D_ * F_;
    const long WQKV = (long)QKVN * D_;

    for (int blk = 0; blk < NBLOCKS; blk++) {
        // ---- attention ----
        ln_kernel<<<M_/4, 128>>>(x, g1, be1, lns, MD);                   // 3 (blk 0)

        gemm_mma<3><<<dim3(QKVN/128, M_/128), 512, SMG>>>(               // 4 (blk 0) <- ncu
            lns, wqkv, bqkv, qkvs, D_, D_, D_, QKVN, MD, WQKV, MQ);

        flash_attn<<<dim3(N_/128, B_*H_), 256, SMF>>>(qkvs, x, MQ);

        // ---- MLP ----
        ln_kernel<<<M_/4, 128>>>(x, g2, be2, lns, MD);

        // MLP1: split-K x3 into three fp32 buffers (4 dense waves of 296)
        gemm_mma<0><<<dim3(F_/128, M_/128, 3), 512, SMG>>>(
            lns, w0t, nullptr, ffw, D_/3, D_, D_, F_, MD, WDF, MF);

        gelu_split<<<(int)(MF/1024), 256>>>(ffw, ffw + MF, ffw + 2*MF, b0, ffs, MF);

        // MLP2: split-K x3 (288 CTAs = one full wave), red.add residual into x
        gemm_mma<5><<<dim3(D_/128, M_/128, 3), 512, SMG>>>(
            ffs, w1t, b1, x, F_/3, F_, F_, D_, MF, WDF, 0);
    }
    (void)in_sizes; (void)n_in; (void)out_size;
}

// round 11
// speedup vs baseline: 1.2684x; 1.2684x over previous
#include <cuda_runtime.h>
#include <cuda_bf16.h>
#include <cuda_fp16.h>
#include <math.h>
#include <stdint.h>

// Problem constants
#define B_  4
#define N_  512
#define D_  768
#define F_  3072
#define H_  12
#define HD_ 64
#define M_  (B_*N_)   // 2048 tokens
#define NBLOCKS 12
#define QKVN (3*D_)   // 2304

// =================== scratch (static device globals) ========================
// lns: bf16 split planes (attention LN) OR fp16 split planes (MLP LN) — same bytes
__device__ __align__(256) __nv_bfloat16 g_lns [2L*M_*D_];
__device__ __align__(256) __nv_bfloat16 g_qkvs[2L*M_*QKVN];   // bf16 split
__device__ __align__(256) __half        g_ffs [2L*M_*F_];     // fp16 split
__device__ __align__(256) float         g_ffw [3L*M_*F_];     // split-K fp32 partials
__device__ __align__(256) __nv_bfloat16 g_wqkv[2L*QKVN*D_];   // bf16 split
__device__ __align__(256) __half        g_w0t [(long)D_*F_];  // fp16 single plane
__device__ __align__(256) __half        g_w1t [(long)D_*F_];  // fp16 single plane
__device__ float g_bqkv[QKVN];

// =================== PTX helpers ===========================================
__device__ __forceinline__ uint32_t smem_u32(const void* p){
    uint32_t a;
    asm("{ .reg .u64 t; cvta.to.shared.u64 t, %1; cvt.u32.u64 %0, t; }" : "=r"(a) : "l"(p));
    return a;
}
__device__ __forceinline__ void cpa16(uint32_t d, const void* s){
    asm volatile("cp.async.cg.shared.global [%0], [%1], 16;" :: "r"(d), "l"(s));
}
#define CP_COMMIT() asm volatile("cp.async.commit_group;" ::: "memory")

__device__ __forceinline__ void ldsm4(uint32_t* r, uint32_t addr){
    asm volatile("ldmatrix.sync.aligned.m8n8.x4.shared.b16 {%0,%1,%2,%3}, [%4];"
                 : "=r"(r[0]), "=r"(r[1]), "=r"(r[2]), "=r"(r[3]) : "r"(addr));
}
__device__ __forceinline__ void ldsm4t(uint32_t* r, uint32_t addr){
    asm volatile("ldmatrix.sync.aligned.m8n8.x4.trans.shared.b16 {%0,%1,%2,%3}, [%4];"
                 : "=r"(r[0]), "=r"(r[1]), "=r"(r[2]), "=r"(r[3]) : "r"(addr));
}
__device__ __forceinline__ void mma16816(float* c, const uint32_t* a, const uint32_t* b){
    asm volatile(
        "mma.sync.aligned.m16n8k16.row.col.f32.bf16.bf16.f32 "
        "{%0,%1,%2,%3}, {%4,%5,%6,%7}, {%8,%9}, {%0,%1,%2,%3};"
        : "+f"(c[0]), "+f"(c[1]), "+f"(c[2]), "+f"(c[3])
        : "r"(a[0]), "r"(a[1]), "r"(a[2]), "r"(a[3]), "r"(b[0]), "r"(b[1]));
}
__device__ __forceinline__ void mma16816h(float* c, const uint32_t* a, const uint32_t* b){
    asm volatile(
        "mma.sync.aligned.m16n8k16.row.col.f32.f16.f16.f32 "
        "{%0,%1,%2,%3}, {%4,%5,%6,%7}, {%8,%9}, {%0,%1,%2,%3};"
        : "+f"(c[0]), "+f"(c[1]), "+f"(c[2]), "+f"(c[3])
        : "r"(a[0]), "r"(a[1]), "r"(a[2]), "r"(a[3]), "r"(b[0]), "r"(b[1]));
}
__device__ __forceinline__ void redg2(float* p, float a, float b){
    asm volatile("red.global.v2.f32.add [%0], {%1, %2};" :: "l"(p), "f"(a), "f"(b) : "memory");
}
__device__ __forceinline__ float gelu_exact(float v){
    return 0.5f * v * (1.0f + erff(v * 0.70710678118654752f));
}
__device__ __forceinline__ uint32_t swz(uint32_t off){ return off ^ ((off >> 3) & 0x70); }
// bf16 packers
__device__ __forceinline__ uint32_t pkh(float x, float y){
    __nv_bfloat162 h; h.x = __float2bfloat16(x); h.y = __float2bfloat16(y);
    return *(uint32_t*)&h;
}
__device__ __forceinline__ uint32_t pkl(float x, float y){
    float rx = x - __bfloat162float(__float2bfloat16(x));
    float ry = y - __bfloat162float(__float2bfloat16(y));
    __nv_bfloat162 h; h.x = __float2bfloat16(rx); h.y = __float2bfloat16(ry);
    return *(uint32_t*)&h;
}
// fp16 packers
__device__ __forceinline__ uint32_t pkh16(float x, float y){
    __half2 h; h.x = __float2half_rn(x); h.y = __float2half_rn(y);
    return *(uint32_t*)&h;
}
__device__ __forceinline__ uint32_t pkl16(float x, float y){
    float rx = x - __half2float(__float2half_rn(x));
    float ry = y - __half2float(__float2half_rn(y));
    __half2 h; h.x = __float2half_rn(rx); h.y = __float2half_rn(ry);
    return *(uint32_t*)&h;
}

// =================== LayerNorm: warp per row, 4 rows/CTA ====================
// H16OUT=false: bf16 split planes; true: fp16 split planes (same byte layout)
template<bool H16OUT>
__global__ void __launch_bounds__(128)
ln_kernel(const float* __restrict__ x,
          const float* __restrict__ g,
          const float* __restrict__ be,
          uint16_t* __restrict__ out, long plane)
{
    const int w = threadIdx.x >> 5, l = threadIdx.x & 31;
    const long row = (long)blockIdx.x * 4 + w;
    const float* xr = x + row * D_;

    float4 v[6];
    float s = 0.f;
    #pragma unroll
    for (int i = 0; i < 6; i++) {
        v[i] = *(const float4*)(xr + i * 128 + l * 4);
        s += v[i].x + v[i].y + v[i].z + v[i].w;
    }
    #pragma unroll
    for (int o = 16; o > 0; o >>= 1) s += __shfl_xor_sync(0xFFFFFFFFu, s, o);
    const float mu = s * (1.0f / D_);

    float vs = 0.f;
    #pragma unroll
    for (int i = 0; i < 6; i++) {
        float a = v[i].x - mu, b2 = v[i].y - mu, c = v[i].z - mu, d = v[i].w - mu;
        vs += a*a + b2*b2 + c*c + d*d;
    }
    #pragma unroll
    for (int o = 16; o > 0; o >>= 1) vs += __shfl_xor_sync(0xFFFFFFFFu, vs, o);
    const float inv = rsqrtf(vs * (1.0f / D_) + 1e-5f);

    uint16_t* orow = out + row * D_;
    #pragma unroll
    for (int i = 0; i < 6; i++) {
        const int col = i * 128 + l * 4;
        float4 gg = *(const float4*)(g  + col);
        float4 bb = *(const float4*)(be + col);
        float y0 = (v[i].x - mu) * inv * gg.x + bb.x;
        float y1 = (v[i].y - mu) * inv * gg.y + bb.y;
        float y2 = (v[i].z - mu) * inv * gg.z + bb.z;
        float y3 = (v[i].w - mu) * inv * gg.w + bb.w;
        uint2 hp, lp;
        if (H16OUT) { hp.x = pkh16(y0, y1); hp.y = pkh16(y2, y3);
                      lp.x = pkl16(y0, y1); lp.y = pkl16(y2, y3); }
        else        { hp.x = pkh(y0, y1);   hp.y = pkh(y2, y3);
                      lp.x = pkl(y0, y1);   lp.y = pkl(y2, y3); }
        *(uint2*)(orow + col) = hp;
        *(uint2*)(orow + plane + col) = lp;
    }
}

// =================== Weight transpose + split (batched) =====================
__device__ __forceinline__ void tsplit_tile(const float* __restrict__ in,
                                            __nv_bfloat16* __restrict__ out,
                                            int ldin, int ldout, long plane,
                                            int c0, int r0, int tx, int ty,
                                            float (*t)[33])
{
    #pragma unroll
    for (int i = 0; i < 32; i += 8)
        t[ty+i][tx] = in[(long)(r0+ty+i) * ldin + c0 + tx];
    __syncthreads();
    #pragma unroll
    for (int i = 0; i < 32; i += 8) {
        float v = t[tx][ty+i];
        __nv_bfloat16 h = __float2bfloat16(v);
        long o = (long)(c0+ty+i) * ldout + r0 + tx;
        out[o] = h;
        out[o + plane] = __float2bfloat16(v - __bfloat162float(h));
    }
}

// single-plane fp16 transpose (for MLP weights)
__device__ __forceinline__ void tsplit_tile16(const float* __restrict__ in,
                                              __half* __restrict__ out,
                                              int ldin, int ldout,
                                              int c0, int r0, int tx, int ty,
                                              float (*t)[33])
{
    #pragma unroll
    for (int i = 0; i < 32; i += 8)
        t[ty+i][tx] = in[(long)(r0+ty+i) * ldin + c0 + tx];
    __syncthreads();
    #pragma unroll
    for (int i = 0; i < 32; i += 8) {
        long o = (long)(c0+ty+i) * ldout + r0 + tx;
        out[o] = __float2half_rn(t[tx][ty+i]);
    }
}

// launch 1: Wq/Wk/Wv (z = 0/1/2), bf16 split
__global__ void tsplit_qkv(const float* __restrict__ Wq, const float* __restrict__ Wk,
                           const float* __restrict__ Wv, __nv_bfloat16* __restrict__ out)
{
    __shared__ float t[32][33];
    const int z = blockIdx.z;
    const float* in = (z == 0) ? Wq : (z == 1) ? Wk : Wv;
    tsplit_tile(in, out + (long)z * D_ * D_, D_, D_, (long)QKVN * D_,
                blockIdx.x * 32, blockIdx.y * 32, threadIdx.x, threadIdx.y, t);
}

// launch 2: W0 (z=0, fp16), W1 (z=1, fp16), bias concat (z=2)
__global__ void tsplit_mlp(const float* __restrict__ W0, const float* __restrict__ W1,
                           __half* __restrict__ w0t, __half* __restrict__ w1t,
                           const float* __restrict__ bq, const float* __restrict__ bk,
                           const float* __restrict__ bv, float* __restrict__ bqkv)
{
    __shared__ float t[32][33];
    const int z = blockIdx.z;
    if (z == 2) {
        if (blockIdx.y == 0) {
            int i = blockIdx.x * 256 + threadIdx.y * 32 + threadIdx.x;
            if (i < QKVN)
                bqkv[i] = (i < D_) ? bq[i] : (i < 2*D_) ? bk[i - D_] : bv[i - 2*D_];
        }
        return;
    }
    const int bx = z ? blockIdx.y : blockIdx.x;
    const int by = z ? blockIdx.x : blockIdx.y;
    if (z == 0)
        tsplit_tile16(W0, w0t, F_, D_, bx * 32, by * 32, threadIdx.x, threadIdx.y, t);
    else
        tsplit_tile16(W1, w1t, D_, F_, bx * 32, by * 32, threadIdx.x, threadIdx.y, t);
}

// =================== GELU + split combine (MLP1 split-K x3, fp16 out) ======
__global__ void __launch_bounds__(256)
gelu_split(const float* __restrict__ a, const float* __restrict__ b,
           const float* __restrict__ c,
           const float* __restrict__ bias, __half* __restrict__ out, long plane)
{
    const long i0 = ((long)blockIdx.x * 256 + threadIdx.x) * 4;
    const int col = (int)(i0 % F_);
    float4 va = *(const float4*)(a + i0);
    float4 vb = *(const float4*)(b + i0);
    float4 vc = *(const float4*)(c + i0);
    float4 bs = *(const float4*)(bias + col);
    float y0 = gelu_exact(va.x + vb.x + vc.x + bs.x);
    float y1 = gelu_exact(va.y + vb.y + vc.y + bs.y);
    float y2 = gelu_exact(va.z + vb.z + vc.z + bs.z);
    float y3 = gelu_exact(va.w + vb.w + vc.w + bs.w);
    uint2 hp; hp.x = pkh16(y0, y1); hp.y = pkh16(y2, y3);
    *(uint2*)(out + i0) = hp;
    uint2 lp; lp.x = pkl16(y0, y1); lp.y = pkl16(y2, y3);
    *(uint2*)(out + plane + i0) = lp;
}

// =================== HMMA GEMM, 3-stage pipeline, 2 CTAs/SM ================
// H16=false: bf16, 3 passes (A hi/lo, B hi/lo planes).
// H16=true : fp16, 2 passes: (Ah + Al) @ B  — A split fp16, B single fp16.
// EPI 0: fp32 C[z-buffer] = v | EPI 3: split-bf16 C = v + bias
// EPI 5: fp32 red.add(C, v [+ bias if z==0])
template<int EPI, bool H16>
__global__ void __launch_bounds__(256, 2)
gemm_mma(const uint16_t* __restrict__ A, const uint16_t* __restrict__ B,
         const float* __restrict__ bias, void* __restrict__ Cv,
         int K, int lda, int ldb, int ldc,
         long planeA, long planeB, long planeC)
{
    extern __shared__ char sm[];
    constexpr int ABYTES = 128 * 128;
    constexpr int BBYTES = 128 * 128;
    constexpr int STG = ABYTES + BBYTES;

    const uint32_t smb = (smem_u32(sm) + 127) & ~127u;

    const int tid = threadIdx.x;
    const int wid = tid >> 5, l = tid & 31;
    const int wm = (wid & 3) * 32;
    const int wn = (wid >> 2) * 64;

    const long bm = (long)blockIdx.y * 128;
    const long bn = (long)blockIdx.x * 128;
    const long koff = (long)blockIdx.z * K;

    float* Cf = (float*)Cv;
    if (EPI == 0) Cf += (long)blockIdx.z * planeC;
    __nv_bfloat16* Cb = (__nv_bfloat16*)Cv;

    const int kch = K / 64;
    const int NC = (H16 ? 2 : 3) * kch;

    float acc[2][8][4];
    #pragma unroll
    for (int i = 0; i < 2; i++)
        #pragma unroll
        for (int j = 0; j < 8; j++)
            #pragma unroll
            for (int q = 0; q < 4; q++) acc[i][j][q] = 0.f;

    auto load_chunk = [&](int c, int st) {
        const int p  = c / kch;
        const long kk = koff + (long)(c - p * kch) * 64;
        const uint16_t* Ap;
        const uint16_t* Bp;
        if (H16) {
            Ap = A + ((p == 1) ? planeA : 0) + kk;
            Bp = B + kk;
        } else {
            Ap = A + ((p == 2) ? planeA : 0) + kk;
            Bp = B + ((p == 1) ? planeB : 0) + kk;
        }
        const uint32_t sA = smb + st * STG;
        const uint32_t sB = sA + ABYTES;
        #pragma unroll
        for (int j = 0; j < 4; j++) {
            int idx = tid * 4 + j;
            int row = idx >> 3, c16 = (idx & 7) * 16;
            cpa16(sA + swz(row * 128 + c16),
                  (const char*)(Ap + (bm + row) * lda) + c16);
        }
        #pragma unroll
        for (int j = 0; j < 4; j++) {
            int idx = tid * 4 + j;
            int row = idx >> 3, c16 = (idx & 7) * 16;
            cpa16(sB + swz(row * 128 + c16),
                  (const char*)(Bp + (bn + row) * ldb) + c16);
        }
        CP_COMMIT();
    };

    auto compute = [&](int st) {
        const uint32_t bA = smb + st * STG;
        const uint32_t bB = bA + ABYTES;
        #pragma unroll
        for (int kk2 = 0; kk2 < 4; kk2++) {
            uint32_t a[2][4];
            #pragma unroll
            for (int tm = 0; tm < 2; tm++) {
                int row = wm + tm * 16 + (l & 15);
                uint32_t off = row * 128 + kk2 * 32 + ((l >> 4) * 16);
                ldsm4(a[tm], bA + swz(off));
            }
            #pragma unroll
            for (int nb = 0; nb < 4; nb++) {
                uint32_t b[4];
                int rowB = wn + nb * 16 + (l & 7) + ((l >> 4) << 3);
                uint32_t off = rowB * 128 + kk2 * 32 + (((l >> 3) & 1) * 16);
                ldsm4(b, bB + swz(off));
                #pragma unroll
                for (int tm = 0; tm < 2; tm++) {
                    if (H16) {
                        mma16816h(acc[tm][2*nb],   a[tm], b);
                        mma16816h(acc[tm][2*nb+1], a[tm], b + 2);
                    } else {
                        mma16816(acc[tm][2*nb],   a[tm], b);
                        mma16816(acc[tm][2*nb+1], a[tm], b + 2);
                    }
                }
            }
        }
    };

    load_chunk(0, 0);
    load_chunk(1, 1);
    for (int c = 0; c < NC; c++) {
        if (c < NC - 1) asm volatile("cp.async.wait_group 1;" ::: "memory");
        else            asm volatile("cp.async.wait_group 0;" ::: "memory");
        __syncthreads();
        if (c + 2 < NC) load_chunk(c + 2, (c + 2) % 3);
        compute(c % 3);
    }

    // -------- epilogue --------
    const bool addb = (EPI != 5) || (blockIdx.z == 0);
    #pragma unroll
    for (int tm = 0; tm < 2; tm++) {
        #pragma unroll
        for (int nf = 0; nf < 8; nf++) {
            const long col = bn + wn + nf * 8 + (l & 3) * 2;
            const float bb0 = (bias && addb) ? bias[col]     : 0.f;
            const float bb1 = (bias && addb) ? bias[col + 1] : 0.f;
            #pragma unroll
            for (int h = 0; h < 2; h++) {
                const long row = bm + wm + tm * 16 + (l >> 2) + h * 8;
                float v0 = acc[tm][nf][2*h]     + bb0;
                float v1 = acc[tm][nf][2*h + 1] + bb1;
                const long idx = row * (long)ldc + col;
                if (EPI == 0) {
                    float2 t; t.x = v0; t.y = v1;
                    *(float2*)(Cf + idx) = t;
                } else if (EPI == 5) {
                    redg2(Cf + idx, v0, v1);
                } else {
                    __nv_bfloat16 h0 = __float2bfloat16(v0);
                    __nv_bfloat16 h1 = __float2bfloat16(v1);
                    __nv_bfloat162 hv; hv.x = h0; hv.y = h1;
                    *(__nv_bfloat162*)(Cb + idx) = hv;
                    __nv_bfloat162 lv;
                    lv.x = __float2bfloat16(v0 - __bfloat162float(h0));
                    lv.y = __float2bfloat16(v1 - __bfloat162float(h1));
                    *(__nv_bfloat162*)(Cb + idx + planeC) = lv;
                }
            }
        }
    }
}

// =================== Fused flash attention (bf16 3-pass, unchanged) ========
__global__ void __launch_bounds__(256, 2)
flash_attn(const __nv_bfloat16* __restrict__ qkv, float* __restrict__ x, long planeQ)
{
    extern __shared__ char sm[];
    const uint32_t smb = (smem_u32(sm) + 127) & ~127u;
    const uint32_t Qb = smb;             // Q: hi 16K + lo 16K
    const uint32_t St = smb + 32768;     // 2 stages x 32K

    const int tid = threadIdx.x, wid = tid >> 5, l = tid & 31;
    const int qt = blockIdx.x, z = blockIdx.y;
    const int b = z / H_, h = z % H_;
    const long tokq = (long)b * N_ + qt * 128;

    #pragma unroll
    for (int p = 0; p < 2; p++)
        #pragma unroll
        for (int j = 0; j < 4; j++) {
            int idx = tid * 4 + j;
            int row = idx >> 3, c16 = idx & 7;
            cpa16(Qb + p*16384 + swz(row*128 + c16*16),
                  qkv + p*planeQ + (tokq + row)*QKVN + h*HD_ + c16*8);
        }

    auto load_kv = [&](int c, int st) {
        const uint32_t base = St + st * 32768;
        #pragma unroll
        for (int p = 0; p < 2; p++)
            #pragma unroll
            for (int j = 0; j < 2; j++) {
                int idx = tid * 2 + j;
                int row = idx >> 3, c16 = idx & 7;
                const long tok = (long)b * N_ + c * 64 + row;
                cpa16(base + p*8192 + swz(row*128 + c16*16),
                      qkv + p*planeQ + tok*QKVN + D_ + h*HD_ + c16*8);
                cpa16(base + 16384 + p*8192 + swz(row*128 + c16*16),
                      qkv + p*planeQ + tok*QKVN + 2*D_ + h*HD_ + c16*8);
            }
        CP_COMMIT();
    };

    load_kv(0, 0);
    load_kv(1, 1);

    float o[8][4];
    #pragma unroll
    for (int i = 0; i < 8; i++)
        #pragma unroll
        for (int q = 0; q < 4; q++) o[i][q] = 0.f;
    float m0 = -1e30f, m1 = -1e30f, rs0 = 0.f, rs1 = 0.f;

    const int NCH = N_ / 64;   // 8
    for (int c = 0; c < NCH; c++) {
        if (c < NCH - 1) asm volatile("cp.async.wait_group 1;" ::: "memory");
        else             asm volatile("cp.async.wait_group 0;" ::: "memory");
        __syncthreads();

        const uint32_t Kst = St + (c & 1) * 32768;
        const uint32_t Vst = Kst + 16384;

        float s[8][4];
        #pragma unroll
        for (int i = 0; i < 8; i++)
            #pragma unroll
            for (int q = 0; q < 4; q++) s[i][q] = 0.f;

        #pragma unroll
        for (int kk = 0; kk < 4; kk++) {
            uint32_t ah[4], al[4];
            {
                int row = wid * 16 + (l & 15);
                uint32_t off = row * 128 + kk * 32 + ((l >> 4) * 16);
                ldsm4(ah, Qb + swz(off));
                ldsm4(al, Qb + 16384 + swz(off));
            }
            #pragma unroll
            for (int nb = 0; nb < 4; nb++) {
                int rowB = nb * 16 + (l & 7) + ((l >> 4) << 3);
                uint32_t off = rowB * 128 + kk * 32 + (((l >> 3) & 1) * 16);
                uint32_t bh[4], bl[4];
                ldsm4(bh, Kst + swz(off));
                ldsm4(bl, Kst + 8192 + swz(off));
                mma16816(s[2*nb],   ah, bh); mma16816(s[2*nb+1], ah, bh + 2);
                mma16816(s[2*nb],   ah, bl); mma16816(s[2*nb+1], ah, bl + 2);
                mma16816(s[2*nb],   al, bh); mma16816(s[2*nb+1], al, bh + 2);
            }
        }
        #pragma unroll
        for (int i = 0; i < 8; i++)
            #pragma unroll
            for (int q = 0; q < 4; q++) s[i][q] *= 0.125f;

        float mx0 = -1e30f, mx1 = -1e30f;
        #pragma unroll
        for (int i = 0; i < 8; i++) {
            mx0 = fmaxf(mx0, fmaxf(s[i][0], s[i][1]));
            mx1 = fmaxf(mx1, fmaxf(s[i][2], s[i][3]));
        }
        mx0 = fmaxf(mx0, __shfl_xor_sync(0xFFFFFFFFu, mx0, 1));
        mx0 = fmaxf(mx0, __shfl_xor_sync(0xFFFFFFFFu, mx0, 2));
        mx1 = fmaxf(mx1, __shfl_xor_sync(0xFFFFFFFFu, mx1, 1));
        mx1 = fmaxf(mx1, __shfl_xor_sync(0xFFFFFFFFu, mx1, 2));
        float nm0 = fmaxf(m0, mx0), nm1 = fmaxf(m1, mx1);
        float sc0 = __expf(m0 - nm0), sc1 = __expf(m1 - nm1);
        m0 = nm0; m1 = nm1;

        float sum0 = 0.f, sum1 = 0.f;
        #pragma unroll
        for (int i = 0; i < 8; i++) {
            s[i][0] = __expf(s[i][0] - m0);
            s[i][1] = __expf(s[i][1] - m0);
            s[i][2] = __expf(s[i][2] - m1);
            s[i][3] = __expf(s[i][3] - m1);
            sum0 += s[i][0] + s[i][1];
            sum1 += s[i][2] + s[i][3];
        }
        sum0 += __shfl_xor_sync(0xFFFFFFFFu, sum0, 1);
        sum0 += __shfl_xor_sync(0xFFFFFFFFu, sum0, 2);
        sum1 += __shfl_xor_sync(0xFFFFFFFFu, sum1, 1);
        sum1 += __shfl_xor_sync(0xFFFFFFFFu, sum1, 2);
        rs0 = rs0 * sc0 + sum0;
        rs1 = rs1 * sc1 + sum1;

        #pragma unroll
        for (int i = 0; i < 8; i++) {
            o[i][0] *= sc0; o[i][1] *= sc0;
            o[i][2] *= sc1; o[i][3] *= sc1;
        }

        #pragma unroll
        for (int kc = 0; kc < 4; kc++) {
            uint32_t ah[4], al[4];
            ah[0] = pkh(s[2*kc][0],   s[2*kc][1]);
            ah[1] = pkh(s[2*kc][2],   s[2*kc][3]);
            ah[2] = pkh(s[2*kc+1][0], s[2*kc+1][1]);
            ah[3] = pkh(s[2*kc+1][2], s[2*kc+1][3]);
            al[0] = pkl(s[2*kc][0],   s[2*kc][1]);
            al[1] = pkl(s[2*kc][2],   s[2*kc][3]);
            al[2] = pkl(s[2*kc+1][0], s[2*kc+1][1]);
            al[3] = pkl(s[2*kc+1][2], s[2*kc+1][3]);
            #pragma unroll
            for (int nb = 0; nb < 4; nb++) {
                uint32_t off = (kc*16 + (l & 15)) * 128 + nb*32 + ((l >> 4) * 16);
                uint32_t bh[4], bl[4];
                ldsm4t(bh, Vst + swz(off));
                ldsm4t(bl, Vst + 8192 + swz(off));
                mma16816(o[2*nb],   ah, bh); mma16816(o[2*nb+1], ah, bh + 2);
                mma16816(o[2*nb],   ah, bl); mma16816(o[2*nb+1], ah, bl + 2);
                mma16816(o[2*nb],   al, bh); mma16816(o[2*nb+1], al, bh + 2);
            }
        }

        __syncthreads();
        if (c + 2 < NCH) load_kv(c + 2, c & 1);
    }

    const float inv0 = 1.f / rs0, inv1 = 1.f / rs1;
    const long tok0 = tokq + wid * 16 + (l >> 2);
    const long col = h * HD_ + (l & 3) * 2;
    #pragma unroll
    for (int nf = 0; nf < 8; nf++) {
        float2* p0 = (float2*)(x + tok0 * D_ + col + nf * 8);
        float2 t0 = *p0;
        t0.x += o[nf][0] * inv0; t0.y += o[nf][1] * inv0;
        *p0 = t0;
        float2* p1 = (float2*)(x + (tok0 + 8) * D_ + col + nf * 8);
        float2 t1 = *p1;
        t1.x += o[nf][2] * inv1; t1.y += o[nf][3] * inv1;
        *p1 = t1;
    }
}

// =================== driver ================================================
extern "C" void kernel_launch(void* const* d_in, const int* in_sizes, int n_in,
                              void* d_out, int out_size)
{
    const float* x0  = (const float*)d_in[0];
    const float* Wq  = (const float*)d_in[1];
    const float* bq  = (const float*)d_in[2];
    const float* Wk  = (const float*)d_in[3];
    const float* bk  = (const float*)d_in[4];
    const float* Wv  = (const float*)d_in[5];
    const float* bv  = (const float*)d_in[6];
    const float* g1  = (const float*)d_in[7];
    const float* be1 = (const float*)d_in[8];
    const float* g2  = (const float*)d_in[9];
    const float* be2 = (const float*)d_in[10];
    const float* W0  = (const float*)d_in[11];
    const float* b0  = (const float*)d_in[12];
    const float* W1  = (const float*)d_in[13];
    const float* b1  = (const float*)d_in[14];

    float* x = (float*)d_out;

    __nv_bfloat16 *lns, *qkvs, *wqkv;
    __half *ffs, *w0t, *w1t;
    float *bqkv, *ffw;
    cudaGetSymbolAddress((void**)&lns,  g_lns);
    cudaGetSymbolAddress((void**)&qkvs, g_qkvs);
    cudaGetSymbolAddress((void**)&ffs,  g_ffs);
    cudaGetSymbolAddress((void**)&ffw,  g_ffw);
    cudaGetSymbolAddress((void**)&wqkv, g_wqkv);
    cudaGetSymbolAddress((void**)&w0t,  g_w0t);
    cudaGetSymbolAddress((void**)&w1t,  g_w1t);
    cudaGetSymbolAddress((void**)&bqkv, g_bqkv);

    const int SMG = 3 * (128*128 + 128*128) + 256;   // 98560
    const int SMF = 32768 + 2 * 32768 + 256;          // 98560
    cudaFuncSetAttribute(gemm_mma<3,false>, cudaFuncAttributeMaxDynamicSharedMemorySize, SMG);
    cudaFuncSetAttribute(gemm_mma<0,true>,  cudaFuncAttributeMaxDynamicSharedMemorySize, SMG);
    cudaFuncSetAttribute(gemm_mma<5,true>,  cudaFuncAttributeMaxDynamicSharedMemorySize, SMG);
    cudaFuncSetAttribute(flash_attn,  cudaFuncAttributeMaxDynamicSharedMemorySize, SMF);

    cudaMemcpyAsync(x, x0, sizeof(float)*M_*D_, cudaMemcpyDeviceToDevice);

    // ---- weight preprocessing: 2 launches so captured #4 = QKV GEMM ----
    dim3 tb(32, 8);
    tsplit_qkv<<<dim3(D_/32, D_/32, 3), tb>>>(Wq, Wk, Wv, wqkv);                 // 1
    tsplit_mlp<<<dim3(F_/32, D_/32, 3), tb>>>(W0, W1, w0t, w1t, bq, bk, bv, bqkv); // 2

    const long MD   = (long)M_ * D_;
    const long MQ   = (long)M_ * QKVN;
    const long MF   = (long)M_ * F_;
    const long WQKV = (long)QKVN * D_;

    for (int blk = 0; blk < NBLOCKS; blk++) {
        // ---- attention (bf16 3-pass) ----
        ln_kernel<false><<<M_/4, 128>>>(x, g1, be1, (uint16_t*)lns, MD);   // 3 (blk 0)

        gemm_mma<3,false><<<dim3(QKVN/128, M_/128), 256, SMG>>>(           // 4 (blk 0) <- ncu
            (const uint16_t*)lns, (const uint16_t*)wqkv, bqkv, qkvs,
            D_, D_, D_, QKVN, MD, WQKV, MQ);

        flash_attn<<<dim3(N_/128, B_*H_), 256, SMF>>>(qkvs, x, MQ);

        // ---- MLP (fp16 2-pass) ----
        ln_kernel<true><<<M_/4, 128>>>(x, g2, be2, (uint16_t*)lns, MD);

        // MLP1: split-K x3 into three fp32 buffers
        gemm_mma<0,true><<<dim3(F_/128, M_/128, 3), 256, SMG>>>(
            (const uint16_t*)lns, (const uint16_t*)w0t, nullptr, ffw,
            D_/3, D_, D_, F_, MD, 0, MF);

        gelu_split<<<(int)(MF/1024), 256>>>(ffw, ffw + MF, ffw + 2*MF, b0, ffs, MF);

        // MLP2: split-K x3, red.add residual into x
        gemm_mma<5,true><<<dim3(D_/128, M_/128, 3), 256, SMG>>>(
            (const uint16_t*)ffs, (const uint16_t*)w1t, b1, x,
            F_/3, F_, F_, D_, MF, 0, 0);
    }
    (void)in_sizes; (void)n_in; (void)out_size;
}